// round 1
// baseline (speedup 1.0000x reference)
#include <cuda_runtime.h>
#include <math.h>

#define B 4096
#define FULL 0xffffffffu

// ---------------- scratch (device globals; no allocation allowed) ----------
__device__ float    d_t0[B*14*14*32];   // pooled conv0 output, channel-last
__device__ unsigned d_X1[B*14*14];      // packed sign(h0) bits
__device__ float    d_p1[B*7*7*32];     // maxpool2(h0) shortcut
__device__ float    d_u1[B*7*7*32];     // pooled binary-conv1 sums
__device__ float    d_h1[B*7*7*32];     // bn(u1)+p1
__device__ unsigned d_X2[B*7*7];        // packed sign(h1) bits
__device__ float    d_p2[B*3*3*32];     // maxpool2(h1)
__device__ float    d_u2[B*3*3*32];     // pooled binary-conv2 sums
__device__ unsigned d_W1b[32*9];
__device__ unsigned d_W2b[32*9];

#define NB_STATS 264
__device__ float d_psum[NB_STATS*32];
__device__ float d_pss [NB_STATS*32];
__device__ float d_scale[3*32];
__device__ float d_bias [3*32];

// ---------------- K0: pack binary weights (sign bits) ----------------------
__global__ void packW(const float* __restrict__ w1, const float* __restrict__ w2) {
    int t = threadIdx.x;               // 576 threads
    if (t >= 576) return;
    const float* w = (t < 288) ? w1 : w2;
    unsigned*  dst = (t < 288) ? d_W1b : d_W2b;
    int r = t % 288;
    int o = r / 9, tap = r % 9;
    unsigned word = 0;
#pragma unroll
    for (int c = 0; c < 32; c++)
        word |= (w[o*288 + c*9 + tap] > 0.f ? 1u : 0u) << c;
    dst[o*9 + tap] = word;
}

// ---------------- K1: conv0 (Cin=1, pad=1) fused with 2x2 maxpool ----------
// thread = (b, py, px, c); lane = c; warp shares one pooled pixel.
__global__ void conv0pool(const float* __restrict__ x, const float* __restrict__ w0) {
    int gid = blockIdx.x * blockDim.x + threadIdx.x;   // B*196*32 exact
    int c   = gid & 31;
    int pix = (gid >> 5) % 196;
    int b   = gid / (196 * 32);
    int py = pix / 14, px = pix % 14;

    float w[9];
#pragma unroll
    for (int k = 0; k < 9; k++) w[k] = w0[c*9 + k];

    const float* xb = x + b * 784;
    float xv[4][4];
#pragma unroll
    for (int dy = 0; dy < 4; dy++) {
        int y = 2*py - 1 + dy;
#pragma unroll
        for (int dx = 0; dx < 4; dx++) {
            int xx = 2*px - 1 + dx;
            xv[dy][dx] = (y >= 0 && y < 28 && xx >= 0 && xx < 28) ? xb[y*28 + xx] : 0.f;
        }
    }
    float m = -INFINITY;
#pragma unroll
    for (int dy = 0; dy < 2; dy++)
#pragma unroll
        for (int dx = 0; dx < 2; dx++) {
            float s = 0.f;
#pragma unroll
            for (int ky = 0; ky < 3; ky++)
#pragma unroll
                for (int kx = 0; kx < 3; kx++)
                    s = fmaf(w[ky*3+kx], xv[dy+ky][dx+kx], s);
            m = fmaxf(m, s);
        }
    d_t0[gid] = m;
}

// ---------------- K2: per-channel sum / sumsq partials (deterministic) -----
__global__ void stats_kernel(const float* __restrict__ in, int total) {
    int lane = threadIdx.x & 31;       // == channel (layout channel-last, stride%32==0)
    float s = 0.f, q = 0.f;
    int stride = blockDim.x * gridDim.x;
    for (int i = blockIdx.x * blockDim.x + threadIdx.x; i < total; i += stride) {
        float v = in[i];
        s += v;
        q = fmaf(v, v, q);
    }
    __shared__ float sh_s[8][33], sh_q[8][33];
    int w = threadIdx.x >> 5;
    sh_s[w][lane] = s; sh_q[w][lane] = q;
    __syncthreads();
    if (threadIdx.x < 32) {
        float ts = 0.f, tq = 0.f;
#pragma unroll
        for (int j = 0; j < 8; j++) { ts += sh_s[j][lane]; tq += sh_q[j][lane]; }
        d_psum[blockIdx.x*32 + lane] = ts;
        d_pss [blockIdx.x*32 + lane] = tq;
    }
}

// ---------------- K3: finalize BN -> per-channel scale/bias ----------------
__global__ void finalizeBN(int nb, int total,
                           const float* __restrict__ gamma, const float* __restrict__ beta,
                           int stage) {
    int c = threadIdx.x;               // 32 threads
    double s = 0.0, q = 0.0;
    for (int b = 0; b < nb; b++) { s += (double)d_psum[b*32+c]; q += (double)d_pss[b*32+c]; }
    double n    = (double)total / 32.0;
    double mean = s / n;
    double var  = q / n - mean * mean;
    double sc   = (double)gamma[c] / sqrt(var + 1e-5);
    d_scale[stage*32 + c] = (float)sc;
    d_bias [stage*32 + c] = (float)((double)beta[c] - mean * sc);
}

// ---------------- K4: bn(t0) -> sign-pack X1 + shortcut pool p1 ------------
// warp = (b, py, px) in 7x7; lane = c.
__global__ void pack1() {
    int wid  = (blockIdx.x * blockDim.x + threadIdx.x) >> 5;   // B*49 exact
    int lane = threadIdx.x & 31;
    int b  = wid / 49;
    int r  = wid % 49;
    int py = r / 7, px = r % 7;
    float sc = d_scale[lane], bs = d_bias[lane];
    float hmax = -INFINITY;
    unsigned myw = 0;
#pragma unroll
    for (int d = 0; d < 4; d++) {
        int y = 2*py + (d >> 1), x = 2*px + (d & 1);
        float v = d_t0[((b*14 + y)*14 + x)*32 + lane];
        float h = fmaf(sc, v, bs);
        unsigned bal = __ballot_sync(FULL, h > 0.f);
        if (lane == d) myw = bal;
        hmax = fmaxf(hmax, h);
    }
    if (lane < 4) {
        int y = 2*py + (lane >> 1), x = 2*px + (lane & 1);
        d_X1[(b*14 + y)*14 + x] = myw;
    }
    d_p1[((b*7 + py)*7 + px)*32 + lane] = hmax;
}

// ---------------- K5/K9: binary conv (xor+popc) fused with 2x2 maxpool -----
// S = input spatial size (14 or 7); pooled out = S/2. thread = (b,py,px,o).
template <int S>
__global__ void bconvpool(const unsigned* __restrict__ X,
                          const unsigned* __restrict__ Wb,
                          float* __restrict__ U) {
    constexpr int P = S / 2;
    int gid = blockIdx.x * blockDim.x + threadIdx.x;   // B*P*P*32 exact
    int o   = gid & 31;
    int wid = gid >> 5;
    int b  = wid / (P*P);
    int r  = wid % (P*P);
    int py = r / P, px = r % P;

    unsigned wb[9];
#pragma unroll
    for (int k = 0; k < 9; k++) wb[k] = Wb[o*9 + k];

    const unsigned* Xb = X + b * S * S;
    unsigned xv[4][4];
    bool     vl[4][4];
#pragma unroll
    for (int dy = 0; dy < 4; dy++) {
        int y = 2*py - 1 + dy;
#pragma unroll
        for (int dx = 0; dx < 4; dx++) {
            int xx = 2*px - 1 + dx;
            bool ok = (y >= 0 && y < S && xx >= 0 && xx < S);
            vl[dy][dx] = ok;
            xv[dy][dx] = ok ? Xb[y*S + xx] : 0u;
        }
    }
    int m = -100000;
#pragma unroll
    for (int dy = 0; dy < 2; dy++)
#pragma unroll
        for (int dx = 0; dx < 2; dx++) {
            int acc = 0;
#pragma unroll
            for (int ky = 0; ky < 3; ky++)
#pragma unroll
                for (int kx = 0; kx < 3; kx++)
                    if (vl[dy+ky][dx+kx])
                        acc += 32 - 2 * __popc(xv[dy+ky][dx+kx] ^ wb[ky*3+kx]);
            m = max(m, acc);
        }
    U[gid] = (float)m;
}

// ---------------- K8a: h1 = bn(u1)+p1, store + sign-pack X2 ----------------
__global__ void h1_pack() {
    int i = blockIdx.x * blockDim.x + threadIdx.x;     // B*49*32 exact
    int c = i & 31;
    float v = fmaf(d_scale[32 + c], d_u1[i], d_bias[32 + c]) + d_p1[i];
    d_h1[i] = v;
    unsigned bal = __ballot_sync(FULL, v > 0.f);
    if (c == 0) d_X2[i >> 5] = bal;
}

// ---------------- K8b: p2 = maxpool2(h1) (7 -> 3, floor) -------------------
__global__ void pool_h1() {
    int i = blockIdx.x * blockDim.x + threadIdx.x;     // B*9*32 exact
    int c   = i & 31;
    int wid = i >> 5;
    int b  = wid / 9;
    int r  = wid % 9;
    int py = r / 3, px = r % 3;
    float m = -INFINITY;
#pragma unroll
    for (int dy = 0; dy < 2; dy++)
#pragma unroll
        for (int dx = 0; dx < 2; dx++)
            m = fmaxf(m, d_h1[((b*7 + 2*py + dy)*7 + 2*px + dx)*32 + c]);
    d_p2[i] = m;
}

// ---------------- K11: fused h2 = bn(u2)+p2, flatten, FC -------------------
// warp = one batch element; lane = channel c; 10 lane-parallel dot partials.
__global__ void fc_kernel(const float* __restrict__ fw, const float* __restrict__ fb,
                          float* __restrict__ out) {
    int wid = (blockIdx.x * blockDim.x + threadIdx.x) >> 5;   // b, B exact
    int c   = threadIdx.x & 31;
    float sc = d_scale[64 + c], bs = d_bias[64 + c];
    float acc[10];
#pragma unroll
    for (int k = 0; k < 10; k++) acc[k] = 0.f;
#pragma unroll
    for (int ij = 0; ij < 9; ij++) {
        float h = fmaf(sc, d_u2[(wid*9 + ij)*32 + c], bs) + d_p2[(wid*9 + ij)*32 + c];
#pragma unroll
        for (int k = 0; k < 10; k++)
            acc[k] = fmaf(h, fw[k*288 + c*9 + ij], acc[k]);
    }
#pragma unroll
    for (int k = 0; k < 10; k++) {
#pragma unroll
        for (int off = 16; off; off >>= 1)
            acc[k] += __shfl_xor_sync(FULL, acc[k], off);
        if (c == k) out[wid*10 + k] = acc[k] + fb[k];
    }
}

// ---------------- launch ----------------------------------------------------
extern "C" void kernel_launch(void* const* d_in, const int* in_sizes, int n_in,
                              void* d_out, int out_size) {
    const float* x  = (const float*)d_in[0];
    const float* w0 = (const float*)d_in[1];
    const float* g0 = (const float*)d_in[2];
    const float* b0 = (const float*)d_in[3];
    const float* w1 = (const float*)d_in[4];
    const float* g1 = (const float*)d_in[5];
    const float* b1 = (const float*)d_in[6];
    const float* w2 = (const float*)d_in[7];
    const float* g2 = (const float*)d_in[8];
    const float* b2 = (const float*)d_in[9];
    const float* fw = (const float*)d_in[10];
    const float* fb = (const float*)d_in[11];
    float* out = (float*)d_out;

    unsigned *X1, *X2, *W1b, *W2b;
    float *u1, *u2, *t0;
    cudaGetSymbolAddress((void**)&X1,  d_X1);
    cudaGetSymbolAddress((void**)&X2,  d_X2);
    cudaGetSymbolAddress((void**)&W1b, d_W1b);
    cudaGetSymbolAddress((void**)&W2b, d_W2b);
    cudaGetSymbolAddress((void**)&u1,  d_u1);
    cudaGetSymbolAddress((void**)&u2,  d_u2);
    cudaGetSymbolAddress((void**)&t0,  d_t0);

    const int T0 = B*14*14*32;   // 25,690,112
    const int T1 = B*7*7*32;     //  6,422,528
    const int T2 = B*3*3*32;     //  1,179,648

    packW<<<1, 576>>>(w1, w2);

    conv0pool<<<T0/256, 256>>>(x, w0);
    stats_kernel<<<NB_STATS, 256>>>(t0, T0);
    finalizeBN<<<1, 32>>>(NB_STATS, T0, g0, b0, 0);

    pack1<<<T1/256, 256>>>();
    bconvpool<14><<<T1/256, 256>>>(X1, W1b, u1);
    stats_kernel<<<NB_STATS, 256>>>(u1, T1);
    finalizeBN<<<1, 32>>>(NB_STATS, T1, g1, b1, 1);

    h1_pack<<<T1/256, 256>>>();
    pool_h1<<<T2/256, 256>>>();
    bconvpool<7><<<T2/256, 256>>>(X2, W2b, u2);
    stats_kernel<<<NB_STATS, 256>>>(u2, T2);
    finalizeBN<<<1, 32>>>(NB_STATS, T2, g2, b2, 2);

    fc_kernel<<<(B*32)/256, 256>>>(fw, fb, out);
}

// round 2
// speedup vs baseline: 1.1852x; 1.1852x over previous
#include <cuda_runtime.h>
#include <math.h>

#define B 4096
#define FULL 0xffffffffu
#define NBMAX 4096

// ---------------- scratch (device globals; no allocation allowed) ----------
__device__ float    d_t0[B*14*14*32];   // pooled conv0 output, channel-last
__device__ unsigned d_X1[B*14*14];      // packed sign(h0) bits
__device__ float    d_p1[B*7*7*32];     // maxpool2(h0) shortcut
__device__ short    d_u1[B*7*7*32];     // pooled binary-conv1 sums (exact ints)
__device__ unsigned d_X2[B*7*7];        // packed sign(h1) bits
__device__ float    d_p2[B*3*3*32];     // maxpool2(h1)
__device__ short    d_u2[B*3*3*32];     // pooled binary-conv2 sums
__device__ unsigned d_W1b[32*9];
__device__ unsigned d_W2b[32*9];

__device__ float d_psum[NBMAX*32];
__device__ float d_pss [NBMAX*32];
__device__ float d_scale[3*32];
__device__ float d_bias [3*32];

// ---------------- K0: pack binary weights (sign bits) ----------------------
__global__ void packW(const float* __restrict__ w1, const float* __restrict__ w2) {
    int t = threadIdx.x;               // 576 threads
    if (t >= 576) return;
    const float* w = (t < 288) ? w1 : w2;
    unsigned*  dst = (t < 288) ? d_W1b : d_W2b;
    int r = t % 288;
    int o = r / 9, tap = r % 9;
    unsigned word = 0;
#pragma unroll
    for (int c = 0; c < 32; c++)
        word |= (w[o*288 + c*9 + tap] > 0.f ? 1u : 0u) << c;
    dst[o*9 + tap] = word;
}

// ---------------- K1: conv0 (Cin=1, pad=1) + 2x2 maxpool + fused stats -----
// block = one image; 14 warps, warp = pooled row; lane = out channel.
__global__ void __launch_bounds__(448) conv0pool(const float* __restrict__ x,
                                                 const float* __restrict__ w0) {
    __shared__ float xs[30][32];       // zero-padded 28x28 image (+1 border)
    __shared__ float ws[288];
    __shared__ float ss[14][33], sq[14][33];
    int b = blockIdx.x;
    int t = threadIdx.x;

    for (int i = t; i < 960; i += 448) ((float*)xs)[i] = 0.f;
    if (t < 288) ws[t] = w0[t];
    __syncthreads();
    const float* xb = x + b*784;
    for (int i = t; i < 784; i += 448) {
        int r = i / 28;
        xs[r + 1][i - r*28 + 1] = xb[i];
    }
    __syncthreads();

    int lane = t & 31, w = t >> 5;     // w = pooled row py (0..13)
    float wr[9];
#pragma unroll
    for (int k = 0; k < 9; k++) wr[k] = ws[lane*9 + k];

    float s = 0.f, q = 0.f;
    int py = w;
    float* out = d_t0 + (((long)b*14 + py)*14)*32 + lane;
#pragma unroll
    for (int px2 = 0; px2 < 7; px2++) {
        int c0 = 4*px2;
        float xv[4][6];
#pragma unroll
        for (int r = 0; r < 4; r++)
#pragma unroll
            for (int cc = 0; cc < 6; cc++)
                xv[r][cc] = xs[2*py + r][c0 + cc];
#pragma unroll
        for (int tpx = 0; tpx < 2; tpx++) {
            float m = -INFINITY;
#pragma unroll
            for (int dy = 0; dy < 2; dy++)
#pragma unroll
                for (int dx = 0; dx < 2; dx++) {
                    float acc = 0.f;
#pragma unroll
                    for (int ky = 0; ky < 3; ky++)
#pragma unroll
                        for (int kx = 0; kx < 3; kx++)
                            acc = fmaf(wr[ky*3+kx], xv[dy+ky][2*tpx+dx+kx], acc);
                    m = fmaxf(m, acc);
                }
            out[(2*px2 + tpx)*32] = m;
            s += m; q = fmaf(m, m, q);
        }
    }
    ss[w][lane] = s; sq[w][lane] = q;
    __syncthreads();
    if (t < 32) {
        float ts = 0.f, tq = 0.f;
#pragma unroll
        for (int j = 0; j < 14; j++) { ts += ss[j][lane]; tq += sq[j][lane]; }
        d_psum[b*32 + lane] = ts;
        d_pss [b*32 + lane] = tq;
    }
}

// ---------------- K2: finalize BN (parallel) -> per-channel scale/bias -----
__global__ void __launch_bounds__(1024) finalizeBN(int nb, int total,
                           const float* __restrict__ gamma, const float* __restrict__ beta,
                           int stage) {
    __shared__ double sh_s[32][33], sh_q[32][33];
    int c = threadIdx.x & 31, chunk = threadIdx.x >> 5;   // 32 chunks
    double s = 0.0, q = 0.0;
    for (int i = chunk; i < nb; i += 32) {
        s += (double)d_psum[i*32 + c];
        q += (double)d_pss [i*32 + c];
    }
    sh_s[chunk][c] = s; sh_q[chunk][c] = q;
    __syncthreads();
    if (threadIdx.x < 32) {
        double ts = 0.0, tq = 0.0;
#pragma unroll
        for (int j = 0; j < 32; j++) { ts += sh_s[j][c]; tq += sh_q[j][c]; }
        double n    = (double)total / 32.0;
        double mean = ts / n;
        double var  = tq / n - mean * mean;
        double sc   = (double)gamma[c] / sqrt(var + 1e-5);
        d_scale[stage*32 + c] = (float)sc;
        d_bias [stage*32 + c] = (float)((double)beta[c] - mean * sc);
    }
}

// ---------------- K3: bn(t0) -> sign-pack X1 + shortcut pool p1 ------------
// warp = (b, pooled pixel 7x7); lane = channel.
__global__ void pack1() {
    int wid  = (blockIdx.x * blockDim.x + threadIdx.x) >> 5;   // B*49 exact
    int lane = threadIdx.x & 31;
    int b  = wid / 49;
    int r  = wid % 49;
    int py = r / 7, px = r % 7;
    float sc = d_scale[lane], bs = d_bias[lane];
    float hmax = -INFINITY;
    unsigned myw = 0;
#pragma unroll
    for (int d = 0; d < 4; d++) {
        int y = 2*py + (d >> 1), x = 2*px + (d & 1);
        float v = d_t0[(((long)b*14 + y)*14 + x)*32 + lane];
        float h = fmaf(sc, v, bs);
        unsigned bal = __ballot_sync(FULL, h > 0.f);
        if (lane == d) myw = bal;
        hmax = fmaxf(hmax, h);
    }
    if (lane < 4) {
        int y = 2*py + (lane >> 1), x = 2*px + (lane & 1);
        d_X1[(b*14 + y)*14 + x] = myw;
    }
    d_p1[((b*7 + py)*7 + px)*32 + lane] = hmax;
}

// ---------------- K4/K6: binary conv + pool + fused stats ------------------
template <int S>
__global__ void bconvpool(const unsigned* __restrict__ X,
                          const unsigned* __restrict__ Wb,
                          short* __restrict__ U, int total) {
    constexpr int P = S / 2;
    int lane = threadIdx.x & 31;       // == out channel o (stride mult of 32)
    unsigned wb[9];
#pragma unroll
    for (int k = 0; k < 9; k++) wb[k] = Wb[lane*9 + k];

    float s = 0.f, q = 0.f;
    int stride = blockDim.x * gridDim.x;
    for (int gid = blockIdx.x * blockDim.x + threadIdx.x; gid < total; gid += stride) {
        int wid = gid >> 5;
        int b  = wid / (P*P);
        int r  = wid % (P*P);
        int py = r / P, px = r % P;
        const unsigned* Xb = X + b * S * S;
        unsigned xv[4][4];
        bool     vl[4][4];
#pragma unroll
        for (int dy = 0; dy < 4; dy++) {
            int y = 2*py - 1 + dy;
#pragma unroll
            for (int dx = 0; dx < 4; dx++) {
                int xx = 2*px - 1 + dx;
                bool ok = (y >= 0 && y < S && xx >= 0 && xx < S);
                vl[dy][dx] = ok;
                xv[dy][dx] = ok ? Xb[y*S + xx] : 0u;
            }
        }
        int m = -100000;
#pragma unroll
        for (int dy = 0; dy < 2; dy++)
#pragma unroll
            for (int dx = 0; dx < 2; dx++) {
                int acc = 0;
#pragma unroll
                for (int ky = 0; ky < 3; ky++)
#pragma unroll
                    for (int kx = 0; kx < 3; kx++)
                        if (vl[dy+ky][dx+kx])
                            acc += 32 - 2 * __popc(xv[dy+ky][dx+kx] ^ wb[ky*3+kx]);
                m = max(m, acc);
            }
        U[gid] = (short)m;
        float fm = (float)m;
        s += fm; q = fmaf(fm, fm, q);
    }
    __shared__ float ss[8][33], sq[8][33];
    int w = threadIdx.x >> 5;
    ss[w][lane] = s; sq[w][lane] = q;
    __syncthreads();
    if (threadIdx.x < 32) {
        float ts = 0.f, tq = 0.f;
#pragma unroll
        for (int j = 0; j < 8; j++) { ts += ss[j][lane]; tq += sq[j][lane]; }
        d_psum[blockIdx.x*32 + lane] = ts;
        d_pss [blockIdx.x*32 + lane] = tq;
    }
}

// ---------------- K5: h1 = bn(u1)+p1 -> X2 pack + p2 pool (h1 never stored)-
// 16 warps per image: warps 0..8 = 3x3 pooling windows (cover pixels 0..5 x 0..5),
// warps 9..15 = remaining 13 pixels (X2 only).
__global__ void h1_fuse() {
    int gw   = (blockIdx.x * blockDim.x + threadIdx.x) >> 5;   // B*16 exact
    int lane = threadIdx.x & 31;
    int b = gw >> 4;
    int j = gw & 15;
    float sc = d_scale[32 + lane], bs = d_bias[32 + lane];
    if (j < 9) {
        int py = j / 3, px = j % 3;
        float hmax = -INFINITY;
        unsigned myw = 0;
#pragma unroll
        for (int d = 0; d < 4; d++) {
            int y = 2*py + (d >> 1), x = 2*px + (d & 1);
            int i = ((b*7 + y)*7 + x)*32 + lane;
            float h = fmaf(sc, (float)d_u1[i], bs) + d_p1[i];
            unsigned bal = __ballot_sync(FULL, h > 0.f);
            if (lane == d) myw = bal;
            hmax = fmaxf(hmax, h);
        }
        if (lane < 4) {
            int y = 2*py + (lane >> 1), x = 2*px + (lane & 1);
            d_X2[(b*7 + y)*7 + x] = myw;
        }
        d_p2[((b*3 + py)*3 + px)*32 + lane] = hmax;
    } else {
        int k = j - 9;
#pragma unroll
        for (int e = 0; e < 2; e++) {
            int pi = 2*k + e;
            if (pi < 13) {                       // warp-uniform branch
                int y = (pi < 6) ? pi : 6;
                int x = (pi < 6) ? 6  : (pi - 6);
                int i = ((b*7 + y)*7 + x)*32 + lane;
                float h = fmaf(sc, (float)d_u1[i], bs) + d_p1[i];
                unsigned bal = __ballot_sync(FULL, h > 0.f);
                if (lane == 0) d_X2[(b*7 + y)*7 + x] = bal;
            }
        }
    }
}

// ---------------- K7: fused h2 = bn(u2)+p2, flatten, FC --------------------
__global__ void fc_kernel(const float* __restrict__ fw, const float* __restrict__ fb,
                          float* __restrict__ out) {
    int wid = (blockIdx.x * blockDim.x + threadIdx.x) >> 5;   // = b
    int c   = threadIdx.x & 31;
    float sc = d_scale[64 + c], bs = d_bias[64 + c];
    float acc[10];
#pragma unroll
    for (int k = 0; k < 10; k++) acc[k] = 0.f;
#pragma unroll
    for (int ij = 0; ij < 9; ij++) {
        int i = (wid*9 + ij)*32 + c;
        float h = fmaf(sc, (float)d_u2[i], bs) + d_p2[i];
#pragma unroll
        for (int k = 0; k < 10; k++)
            acc[k] = fmaf(h, fw[k*288 + c*9 + ij], acc[k]);
    }
#pragma unroll
    for (int k = 0; k < 10; k++) {
#pragma unroll
        for (int off = 16; off; off >>= 1)
            acc[k] += __shfl_xor_sync(FULL, acc[k], off);
        if (c == k) out[wid*10 + k] = acc[k] + fb[k];
    }
}

// ---------------- launch ----------------------------------------------------
extern "C" void kernel_launch(void* const* d_in, const int* in_sizes, int n_in,
                              void* d_out, int out_size) {
    const float* x  = (const float*)d_in[0];
    const float* w0 = (const float*)d_in[1];
    const float* g0 = (const float*)d_in[2];
    const float* b0 = (const float*)d_in[3];
    const float* w1 = (const float*)d_in[4];
    const float* g1 = (const float*)d_in[5];
    const float* b1 = (const float*)d_in[6];
    const float* w2 = (const float*)d_in[7];
    const float* g2 = (const float*)d_in[8];
    const float* b2 = (const float*)d_in[9];
    const float* fw = (const float*)d_in[10];
    const float* fb = (const float*)d_in[11];
    float* out = (float*)d_out;

    unsigned *X1, *X2, *W1b, *W2b;
    short *u1, *u2;
    cudaGetSymbolAddress((void**)&X1,  d_X1);
    cudaGetSymbolAddress((void**)&X2,  d_X2);
    cudaGetSymbolAddress((void**)&W1b, d_W1b);
    cudaGetSymbolAddress((void**)&W2b, d_W2b);
    cudaGetSymbolAddress((void**)&u1,  d_u1);
    cudaGetSymbolAddress((void**)&u2,  d_u2);

    const int T0 = B*14*14*32;   // 25,690,112
    const int T1 = B*7*7*32;     //  6,422,528
    const int T2 = B*3*3*32;     //  1,179,648
    const int NB = 1184;         // 8 blocks per SM for grid-stride kernels

    packW<<<1, 576>>>(w1, w2);

    conv0pool<<<B, 448>>>(x, w0);                       // stats: 4096 partials
    finalizeBN<<<1, 1024>>>(B, T0, g0, b0, 0);

    pack1<<<(B*49*32)/256, 256>>>();

    bconvpool<14><<<NB, 256>>>(X1, W1b, u1, T1);        // stats: 1184 partials
    finalizeBN<<<1, 1024>>>(NB, T1, g1, b1, 1);

    h1_fuse<<<(B*16*32)/256, 256>>>();

    bconvpool<7><<<NB, 256>>>(X2, W2b, u2, T2);         // stats: 1184 partials
    finalizeBN<<<1, 1024>>>(NB, T2, g2, b2, 2);

    fc_kernel<<<(B*32)/256, 256>>>(fw, fb, out);
}